// round 15
// baseline (speedup 1.0000x reference)
#include <cuda_runtime.h>
#include <cuda_fp16.h>

#define N_MAX 131072
#define E_MAX 2100000

// scratch (static __device__ arrays; zero-initialized at module load)
__device__ __half g_hh[N_MAX * 64]; // projected features (fp16 storage, fp32 math)
__device__ float g_as[N_MAX * 8];    // a_src per node/head
__device__ float g_ad[N_MAX * 8];    // a_dst per node/head
__device__ float g_wt[64 * 128];     // W transposed: [c][k]
__device__ int   g_deg[N_MAX];       // reset by aggregate (consumer) each call
__device__ int   g_row[N_MAX];       // CSR row start (by dst, unordered bases)
__device__ int   g_cur[N_MAX];
__device__ int   g_csr[E_MAX];       // src node per CSR slot (COMPACT: L2-resident)
__device__ int   g_total;            // reset by aggregate each call

// ---------------------------------------------------------------------------
// 1) in-degree histogram (REDG fire-and-forget) + W transpose on spare threads
__global__ void degree_kernel(const int* __restrict__ ei,
                              const float* __restrict__ W, int E, int N) {
    int tid = blockIdx.x * blockDim.x + threadIdx.x;
    if (tid < 64 * 128) {
        int c = tid & 63;
        int k = tid >> 6;
        g_wt[c * 128 + k] = W[tid];
    }
    int q = (E + 3) >> 2;
    if (tid >= q) return;
    int d0 = -1, d1 = -1, d2 = -1, d3 = -1;
    d0 = ei[E + tid];
    if (tid + q     < E) d1 = ei[E + tid + q];
    if (tid + 2 * q < E) d2 = ei[E + tid + 2 * q];
    if (tid + 3 * q < E) d3 = ei[E + tid + 3 * q];
    if ((unsigned)d0 < (unsigned)N) atomicAdd(&g_deg[d0], 1);
    if ((unsigned)d1 < (unsigned)N) atomicAdd(&g_deg[d1], 1);
    if ((unsigned)d2 < (unsigned)N) atomicAdd(&g_deg[d2], 1);
    if ((unsigned)d3 < (unsigned)N) atomicAdd(&g_deg[d3], 1);
}

// 2) row-base assignment: warp-aggregated atomic offsets (bases unordered = fine)
__global__ void offsets_kernel(int N) {
    int i = blockIdx.x * blockDim.x + threadIdx.x;
    int lane = threadIdx.x & 31;
    int v = (i < N) ? g_deg[i] : 0;
    int xsum = v;
    #pragma unroll
    for (int o = 1; o < 32; o <<= 1) {
        int y = __shfl_up_sync(0xffffffffu, xsum, o);
        if (lane >= o) xsum += y;
    }
    int tot = __shfl_sync(0xffffffffu, xsum, 31);
    int base = 0;
    if (lane == 31) base = atomicAdd(&g_total, tot);
    base = __shfl_sync(0xffffffffu, base, 31);
    if (i < N) {
        int st = base + xsum - v;
        g_row[i] = st;
        g_cur[i] = st;
    }
}

// 3) scatter edges into CSR slots; 4 independent coalesced edges per thread
__global__ void scatter_kernel(const int* __restrict__ ei, int E, int N) {
    int q = (E + 3) >> 2;
    int e = blockIdx.x * blockDim.x + threadIdx.x;
    if (e >= q) return;
    int s0 = 0, s1 = 0, s2 = 0, s3 = 0;
    int d0 = -1, d1 = -1, d2 = -1, d3 = -1;
    s0 = ei[e];           d0 = ei[E + e];
    if (e + q     < E) { s1 = ei[e + q];     d1 = ei[E + e + q]; }
    if (e + 2 * q < E) { s2 = ei[e + 2 * q]; d2 = ei[E + e + 2 * q]; }
    if (e + 3 * q < E) { s3 = ei[e + 3 * q]; d3 = ei[E + e + 3 * q]; }
    if ((unsigned)d0 < (unsigned)N && (unsigned)s0 < (unsigned)N)
        g_csr[atomicAdd(&g_cur[d0], 1)] = s0;
    if ((unsigned)d1 < (unsigned)N && (unsigned)s1 < (unsigned)N)
        g_csr[atomicAdd(&g_cur[d1], 1)] = s1;
    if ((unsigned)d2 < (unsigned)N && (unsigned)s2 < (unsigned)N)
        g_csr[atomicAdd(&g_cur[d2], 1)] = s2;
    if ((unsigned)d3 < (unsigned)N && (unsigned)s3 < (unsigned)N)
        g_csr[atomicAdd(&g_cur[d3], 1)] = s3;
}

// ---------------------------------------------------------------------------
// 4) GEMM h = x@W, warp-uniform W mapping (warp = head), k2-granular inner
//    loop (u64 = 2 k), 4 nodes x 8 channels per thread, fits 128-reg cap.
#define FFMA2(d, a, b) asm("fma.rn.f32x2 %0, %1, %2, %0;" : "+l"(d) : "l"(a), "l"(b))

#define XS2_STRIDE 17   // u64 stride per node: 16 k2 + 1 pad

__global__ __launch_bounds__(256, 2) void gemm_att_kernel(
        const float* __restrict__ x,
        const float* __restrict__ attS,
        const float* __restrict__ attD, int N) {
    __shared__ unsigned long long ws2[64 * 16];           // [c][k2], 8 KB
    __shared__ unsigned long long xs2[128 * XS2_STRIDE];  // [n][k2], 17.4 KB
    int t = threadIdx.x;
    int w = t >> 5;        // warp = head (0..7)
    int l = t & 31;        // lane = node row
    int node0 = blockIdx.x * 128;

    unsigned long long acc[8][4];   // [channel][node j] f32x2-over-k
    #pragma unroll
    for (int c = 0; c < 8; c++)
        #pragma unroll
        for (int j = 0; j < 4; j++) acc[c][j] = 0ull;

    for (int kc = 0; kc < 4; kc++) {       // 4 chunks of 32 k
        __syncthreads();
        #pragma unroll
        for (int p = 0; p < 4; p++) {
            int idx = t + 256 * p;          // 0..1023 = c*16 + k2
            int c  = idx >> 4;
            int k2 = idx & 15;
            ws2[idx] = ((const unsigned long long*)g_wt)[c * 64 + kc * 16 + k2];
        }
        #pragma unroll
        for (int p = 0; p < 4; p++) {
            int idx = t + 256 * p;          // 0..1023
            int nn = idx >> 3;
            int k4 = idx & 7;
            int n = node0 + nn;
            float4 v = make_float4(0.f, 0.f, 0.f, 0.f);
            if (n < N) v = ((const float4*)x)[n * 32 + kc * 8 + k4];
            union { float4 f; unsigned long long u[2]; } cv;
            cv.f = v;
            xs2[nn * XS2_STRIDE + k4 * 2    ] = cv.u[0];
            xs2[nn * XS2_STRIDE + k4 * 2 + 1] = cv.u[1];
        }
        __syncthreads();

        #pragma unroll 4
        for (int k2 = 0; k2 < 16; k2++) {
            unsigned long long wv[8];       // warp-uniform broadcasts
            #pragma unroll
            for (int c = 0; c < 8; c++)
                wv[c] = ws2[(w * 8 + c) * 16 + k2];
            unsigned long long xv[4];
            #pragma unroll
            for (int j = 0; j < 4; j++)
                xv[j] = xs2[(l + 32 * j) * XS2_STRIDE + k2];
            #pragma unroll
            for (int j = 0; j < 4; j++)
                #pragma unroll
                for (int c = 0; c < 8; c++)
                    FFMA2(acc[c][j], xv[j], wv[c]);
        }
    }

    // epilogue: per-thread head reduction (no shuffles), packed fp16 store
    float aS[8], aD[8];
    #pragma unroll
    for (int c = 0; c < 8; c++) { aS[c] = attS[w * 8 + c]; aD[c] = attD[w * 8 + c]; }

    #pragma unroll
    for (int j = 0; j < 4; j++) {
        int n = node0 + l + 32 * j;
        if (n >= N) continue;
        float v[8];
        float ps = 0.f, pd = 0.f;
        #pragma unroll
        for (int c = 0; c < 8; c++) {
            union { unsigned long long u; float2 f; } cv;
            cv.u = acc[c][j];
            v[c] = cv.f.x + cv.f.y;
            ps += v[c] * aS[c];
            pd += v[c] * aD[c];
        }
        union { uint4 u; __half2 h[4]; } pk;
        #pragma unroll
        for (int c = 0; c < 4; c++)
            pk.h[c] = __floats2half2_rn(v[2 * c], v[2 * c + 1]);
        *(uint4*)&g_hh[(long)n * 64 + w * 8] = pk.u;
        g_as[n * 8 + w] = ps;
        g_ad[n * 8 + w] = pd;
    }
}

// ---------------------------------------------------------------------------
// 5) warp-per-node softmax + gather; QUARTER-warp per edge (4 edges/iter):
//    lane = q*8 + l8; lane owns head l8 (8 contiguous channels = 16B uint4).
//    Per 4 edges: 1 shfl + 1 coalesced as-load + 1 LDG.128 + 1 exp per lane.
//    Consumer-resets g_deg / g_total for the next call.
__global__ void aggregate_kernel(const float* __restrict__ bias,
                                 float* __restrict__ out, int N) {
    int warp = (blockIdx.x * blockDim.x + threadIdx.x) >> 5;
    int lane = threadIdx.x & 31;
    if (warp >= N) return;
    int n  = warp;
    int l8 = lane & 7;         // head for this lane
    int q  = lane >> 3;        // quarter: which edge of the group of 4

    float adn = g_ad[n * 8 + l8];
    int rs = g_row[n];
    int re = rs + g_deg[n];
    if (lane == 0) g_deg[n] = 0;                 // reset for next call
    if (warp == 0 && lane == 1) g_total = 0;     // reset for next call

    float a[8];
    #pragma unroll
    for (int c = 0; c < 8; c++) a[c] = 0.f;
    float ssum = 0.f;

    if (q == 0) {   // self loop on quarter 0
        float asn = g_as[n * 8 + l8];
        float e0 = asn + adn;
        e0 = fmaxf(e0, 0.2f * e0);
        float ex = __expf(e0);
        uint4 u = *(const uint4*)&g_hh[(long)n * 64 + l8 * 8];
        ssum = ex;
        #pragma unroll
        for (int c = 0; c < 4; c++) {
            float2 f = __half22float2(*(__half2*)(((unsigned*)&u) + c));
            a[2 * c]     = ex * f.x;
            a[2 * c + 1] = ex * f.y;
        }
    }

    int base = rs;
    for (; base + 32 <= re; base += 32) {        // full batches: no masking
        int sv = g_csr[base + lane];
        #pragma unroll 2
        for (int it = 0; it < 32; it += 4) {
            int s = __shfl_sync(0xffffffffu, sv, it + q);
            float as = g_as[s * 8 + l8];
            uint4 u = *(const uint4*)&g_hh[(long)s * 64 + l8 * 8];
            float e = as + adn;
            e = fmaxf(e, 0.2f * e);
            float xv = __expf(e);
            ssum += xv;
            #pragma unroll
            for (int c = 0; c < 4; c++) {
                float2 f = __half22float2(*(__half2*)(((unsigned*)&u) + c));
                a[2 * c]     += xv * f.x;
                a[2 * c + 1] += xv * f.y;
            }
        }
    }
    if (base < re) {                              // tail batch: masked
        int cnt = re - base;
        int sv = (lane < cnt) ? g_csr[base + lane] : 0;
        for (int it = 0; it < cnt; it += 4) {
            int idx = it + q;
            int s = __shfl_sync(0xffffffffu, sv, idx);
            float as = g_as[s * 8 + l8];
            uint4 u = *(const uint4*)&g_hh[(long)s * 64 + l8 * 8];
            float e = as + adn;
            e = fmaxf(e, 0.2f * e);
            float xv = __expf(e);
            if (idx >= cnt) xv = 0.f;
            ssum += xv;
            #pragma unroll
            for (int c = 0; c < 4; c++) {
                float2 f = __half22float2(*(__half2*)(((unsigned*)&u) + c));
                a[2 * c]     += xv * f.x;
                a[2 * c + 1] += xv * f.y;
            }
        }
    }

    // combine quarters (stride 16, then 8)
    #pragma unroll
    for (int c = 0; c < 8; c++) {
        a[c] += __shfl_down_sync(0xffffffffu, a[c], 16);
        a[c] += __shfl_down_sync(0xffffffffu, a[c], 8);
    }
    ssum += __shfl_down_sync(0xffffffffu, ssum, 16);
    ssum += __shfl_down_sync(0xffffffffu, ssum, 8);

    if (q == 0) {
        float inv = 1.0f / ssum;
        float4 b0 = ((const float4*)bias)[l8 * 2];
        float4 b1 = ((const float4*)bias)[l8 * 2 + 1];
        float4 o0, o1;
        o0.x = a[0] * inv + b0.x;  o0.y = a[1] * inv + b0.y;
        o0.z = a[2] * inv + b0.z;  o0.w = a[3] * inv + b0.w;
        o1.x = a[4] * inv + b1.x;  o1.y = a[5] * inv + b1.y;
        o1.z = a[6] * inv + b1.z;  o1.w = a[7] * inv + b1.w;
        ((float4*)out)[(long)n * 16 + l8 * 2    ] = o0;
        ((float4*)out)[(long)n * 16 + l8 * 2 + 1] = o1;
    }
}

// ---------------------------------------------------------------------------
extern "C" void kernel_launch(void* const* d_in, const int* in_sizes, int n_in,
                              void* d_out, int out_size) {
    const float* x    = (const float*)d_in[0];
    const int*   ei   = (const int*)d_in[1];
    const float* W    = (const float*)d_in[2];
    const float* attS = (const float*)d_in[3];
    const float* attD = (const float*)d_in[4];
    const float* bias = (const float*)d_in[5];
    float*       out  = (float*)d_out;

    int N = in_sizes[0] / 128;
    int E = in_sizes[1] / 2;
    int Eq = (E + 3) / 4;
    int Dg = (Eq > 64 * 128) ? Eq : 64 * 128;

    degree_kernel   <<<(Dg + 255) / 256, 256>>>(ei, W, E, N);
    offsets_kernel  <<<(N + 255) / 256, 256>>>(N);
    scatter_kernel  <<<(Eq + 255) / 256, 256>>>(ei, E, N);
    gemm_att_kernel <<<(N + 127) / 128, 256>>>(x, attS, attD, N);
    aggregate_kernel<<<((long)N * 32 + 255) / 256, 256>>>(bias, out, N);
}